// round 17
// baseline (speedup 1.0000x reference)
#include <cuda_runtime.h>
#include <cstdint>

// ConditionalSplineSQ2D: out[b] = sum_{g,h,c} param[b,g,h,ii]*param[b,g,h,jj]*coef[g,h,c]
// B=4096, G*G=961 cells, P=8, C=36. Pure HBM stream: 126MB read once.
//
// Touch pipeline: each thread's per-b data is ONE 32B-aligned sector, so an
// LDG.32 "touch" into a rotating junk register pulls a future slab into L1
// for 1 reg + 1 issue slot. Touches are REAL scoreboarded loads (unlike
// droppable prefetch hints), 4 rotating regs (unroll-4 -> WAR distance 4)
// keep ~127KB/SM of DRAM pulls in flight (~4x R14). Consumer LDG.128s then
// hit L1 (~39cyc) and need no double-buffer. Thread t = cell t, 36 coefs in
// registers. In-loop warp reduce + part[k][warp] (3.5KB smem keeps the L1
// carveout big for the 4-slab touch window).

#define GG    961
#define CC    36
#define NTHR  992
#define NWARP 31
#define MAXK  28

#define TOUCH(T, p) asm volatile("ld.global.nc.f32 %0, [%1];" : "=f"(T) : "l"(p))

template <int CSTRIDE>
__global__ __launch_bounds__(NTHR, 1)
void sq2d_kernel(const float* __restrict__ param,
                 const float* __restrict__ coef,
                 float* __restrict__ out,
                 int nB, int rstride)
{
    __shared__ float part[MAXK * 32];   // [k][warp]

    const int tid  = threadIdx.x;
    const int lane = tid & 31;
    const int warp = tid >> 5;
    const bool active = (tid < GG);
    const int cell = active ? tid : (GG - 1);      // pad threads dup cell 960

    const int stride = (CSTRIDE > 0) ? CSTRIDE : rstride;
    const uint32_t bstep = (uint32_t)(GG * 32) * (uint32_t)stride;

    // 36 coefficients in registers (0 for pad threads).
    float cf[CC];
#pragma unroll
    for (int c = 0; c < CC; c++)
        cf[c] = active ? coef[cell * CC + c] : 0.0f;

    const int bid = blockIdx.x;
    const int K = (nB - bid + stride - 1) / stride;    // <= 27

    const char* base = (const char*)param + (size_t)cell * 32
                     + (size_t)bid * (size_t)(GG * 32);

    // Prologue: touch slabs 0..3 (rotating junk regs T0..T3).
    float T0, T1, T2, T3;
    {
        const char* tp = base;
        TOUCH(T0, tp);
        if (1 < K) { TOUCH(T1, tp + bstep); }
        if (2 < K) { TOUCH(T2, tp + 2 * (size_t)bstep); }
        if (3 < K) { TOUCH(T3, tp + 3 * (size_t)bstep); }
    }

    const char* cptr = base;                              // consumer, slab j
    const char* tptr = base + 4 * (size_t)bstep;          // touches, slab j+4

#define SUBBODY(S, TREG)                                                      \
    if (j + (S) < K) {                                                        \
        if (j + (S) + 4 < K) { TOUCH(TREG, tptr); }                           \
        float pv[8];                                                          \
        asm volatile("ld.global.nc.v4.f32 {%0,%1,%2,%3}, [%4];"               \
            : "=f"(pv[0]),"=f"(pv[1]),"=f"(pv[2]),"=f"(pv[3]) : "l"(cptr));   \
        asm volatile("ld.global.nc.v4.f32 {%0,%1,%2,%3}, [%4+16];"            \
            : "=f"(pv[4]),"=f"(pv[5]),"=f"(pv[6]),"=f"(pv[7]) : "l"(cptr));   \
        float acc = 0.0f;                                                     \
        int c = 0;                                                            \
        _Pragma("unroll")                                                     \
        for (int i = 0; i < 8; i++) {                                         \
            float q = 0.0f;                                                   \
            _Pragma("unroll")                                                 \
            for (int jj = i; jj < 8; jj++)                                    \
                q = fmaf(cf[c++], pv[jj], q);                                 \
            acc = fmaf(pv[i], q, acc);                                        \
        }                                                                     \
        _Pragma("unroll")                                                     \
        for (int o = 16; o > 0; o >>= 1)                                      \
            acc += __shfl_xor_sync(0xffffffffu, acc, o);                      \
        if (lane == 0) part[(j + (S)) * 32 + warp] = acc;                     \
    }                                                                         \
    tptr += bstep; cptr += bstep;

#pragma unroll 1
    for (int j = 0; j < K; j += 4) {
        SUBBODY(0, T0)
        SUBBODY(1, T1)
        SUBBODY(2, T2)
        SUBBODY(3, T3)
    }
#undef SUBBODY

    // Keep the touch registers formally live (loads are volatile anyway).
    asm volatile("" :: "f"(T0), "f"(T1), "f"(T2), "f"(T3));

    __syncthreads();   // the only block barrier

    // Warp w finalizes b = bid + w*stride.
    if (warp < K) {
        float v = (lane < NWARP) ? part[warp * 32 + lane] : 0.0f;
#pragma unroll
        for (int o = 16; o > 0; o >>= 1)
            v += __shfl_xor_sync(0xffffffffu, v, o);
        if (lane == 0)
            out[bid + warp * stride] = v;
    }
}

extern "C" void kernel_launch(void* const* d_in, const int* in_sizes, int n_in,
                              void* d_out, int out_size)
{
    const float* param = (const float*)d_in[0];   // [B, 31, 31, 8] f32
    const float* coef  = (const float*)d_in[1];   // [31, 31, 36]   f32
    float* out = (float*)d_out;                    // [B] f32

    const int nB = in_sizes[0] / (GG * 8);

    int dev = 0, sms = 0;
    cudaGetDevice(&dev);
    cudaDeviceGetAttribute(&sms, cudaDevAttrMultiProcessorCount, dev);
    if (sms <= 0) sms = 152;

    int grid = sms;
    const int min_grid = (nB + MAXK - 1) / MAXK;   // keep K <= MAXK
    if (grid < min_grid) grid = min_grid;
    if (grid > nB) grid = nB;

    if (grid == 152)
        sq2d_kernel<152><<<grid, NTHR>>>(param, coef, out, nB, grid);
    else if (grid == 148)
        sq2d_kernel<148><<<grid, NTHR>>>(param, coef, out, nB, grid);
    else
        sq2d_kernel<0><<<grid, NTHR>>>(param, coef, out, nB, grid);
}